// round 1
// baseline (speedup 1.0000x reference)
#include <cuda_runtime.h>
#include <cuda_bf16.h>
#include <cstdint>

// Problem constants
#define BB 2
#define LL 2048
#define DD 1024
#define HH 16
#define HD 64
#define NQKV 3072        // 3*H*HD
#define MROWS (BB*LL)    // 4096

// ---------------- scratch (device globals; no allocations allowed) -------
__device__ float g_qkv[MROWS * NQKV];             // [B*L, 3072]
__device__ float g_Q[BB * HH * LL * HD];          // [B,H,L,HD] (rope'd, pre-scaled)
__device__ float g_K[BB * HH * LL * HD];          // [B,H,L,HD] (rope'd)
__device__ float g_V[BB * HH * LL * HD];          // [B,H,L,HD]
__device__ float g_att[MROWS * (HH * HD)];        // [B*L, 1024]

// ---------------- SGEMM: C = A[MxK] * B[KxN] (+bias) ----------------------
// Classic 128x128 tile, 8x8 per thread, BK=16, 256 threads.
template <bool BIAS>
__global__ __launch_bounds__(256)
void sgemm128(const float* __restrict__ A, const float* __restrict__ Bm,
              const float* __restrict__ bias, float* __restrict__ C,
              int M, int N, int K)
{
    constexpr int BM = 128, BN = 128, BK = 16, TM = 8, TN = 8;
    __shared__ float As[BK * BM];   // transposed: As[k][m]
    __shared__ float Bs[BK * BN];

    const int tid   = threadIdx.x;
    const int mBase = blockIdx.y * BM;
    const int nBase = blockIdx.x * BN;
    const int tRow  = tid / (BN / TN);   // 0..15
    const int tCol  = tid % (BN / TN);   // 0..15

    const int aRow = tid / (BK / 4);         // 0..63
    const int aCol = (tid % (BK / 4)) * 4;   // 0,4,8,12
    const int bRow = tid / (BN / 4);         // 0..7
    const int bCol = (tid % (BN / 4)) * 4;   // 0..124

    const float* Aptr = A + (size_t)mBase * K;
    const float* Bptr = Bm + nBase;

    float acc[TM][TN] = {};
    float regM[TM], regN[TN];

    for (int k0 = 0; k0 < K; k0 += BK) {
        // Load A tile (128x16), store transposed into As
        #pragma unroll
        for (int r = 0; r < BM; r += 64) {
            float4 a = *(const float4*)(Aptr + (size_t)(aRow + r) * K + k0 + aCol);
            As[(aCol + 0) * BM + aRow + r] = a.x;
            As[(aCol + 1) * BM + aRow + r] = a.y;
            As[(aCol + 2) * BM + aRow + r] = a.z;
            As[(aCol + 3) * BM + aRow + r] = a.w;
        }
        // Load B tile (16x128)
        #pragma unroll
        for (int r = 0; r < BK; r += 8) {
            float4 b = *(const float4*)(Bptr + (size_t)(k0 + bRow + r) * N + bCol);
            *(float4*)(&Bs[(bRow + r) * BN + bCol]) = b;
        }
        __syncthreads();

        #pragma unroll
        for (int k = 0; k < BK; k++) {
            *(float4*)(&regM[0]) = *(const float4*)(&As[k * BM + tRow * TM + 0]);
            *(float4*)(&regM[4]) = *(const float4*)(&As[k * BM + tRow * TM + 4]);
            *(float4*)(&regN[0]) = *(const float4*)(&Bs[k * BN + tCol * TN + 0]);
            *(float4*)(&regN[4]) = *(const float4*)(&Bs[k * BN + tCol * TN + 4]);
            #pragma unroll
            for (int i = 0; i < TM; i++)
                #pragma unroll
                for (int j = 0; j < TN; j++)
                    acc[i][j] += regM[i] * regN[j];
        }
        __syncthreads();
    }

    #pragma unroll
    for (int i = 0; i < TM; i++) {
        const int m = mBase + tRow * TM + i;
        #pragma unroll
        for (int j = 0; j < TN; j += 4) {
            const int n = nBase + tCol * TN + j;
            float4 v;
            v.x = acc[i][j + 0]; v.y = acc[i][j + 1];
            v.z = acc[i][j + 2]; v.w = acc[i][j + 3];
            if (BIAS) {
                v.x += bias[n + 0]; v.y += bias[n + 1];
                v.z += bias[n + 2]; v.w += bias[n + 3];
            }
            *(float4*)(&C[(size_t)m * N + n]) = v;
        }
    }
}

// --------------- RoPE + reshape [B,L,3*H*HD] -> Q/K/V [B,H,L,HD] ----------
// Scale (HD^-0.5) folded into Q.
__global__ void rope_reshape(const float* __restrict__ qkv,
                             const float* __restrict__ cosT,
                             const float* __restrict__ sinT,
                             float* __restrict__ Qo, float* __restrict__ Ko,
                             float* __restrict__ Vo)
{
    const int idx = blockIdx.x * blockDim.x + threadIdx.x;  // B*L*H*32 threads
    if (idx >= BB * LL * HH * 32) return;
    const int d = idx & 31;
    const int h = (idx >> 5) & (HH - 1);
    const int l = (idx >> 9) & (LL - 1);
    const int b = idx >> 20;   // 32*16*2048 = 2^20

    const float* row = qkv + ((size_t)(b * LL + l)) * NQKV;
    const float c0 = cosT[l * HD + d],      c1 = cosT[l * HD + d + 32];
    const float s0 = sinT[l * HD + d],      s1 = sinT[l * HD + d + 32];

    const float q0 = row[h * HD + d],            q1 = row[h * HD + d + 32];
    const float k0 = row[DD + h * HD + d],       k1 = row[DD + h * HD + d + 32];
    const float v0 = row[2 * DD + h * HD + d],   v1 = row[2 * DD + h * HD + d + 32];

    const float scale = 0.125f;   // 64^-0.5
    const size_t o = ((size_t)(b * HH + h) * LL + l) * HD;
    Qo[o + d]      = (q0 * c0 - q1 * s0) * scale;
    Qo[o + d + 32] = (q1 * c1 + q0 * s1) * scale;
    Ko[o + d]      = k0 * c0 - k1 * s0;
    Ko[o + d + 32] = k1 * c1 + k0 * s1;
    Vo[o + d]      = v0;
    Vo[o + d + 32] = v1;
}

// --------------- Causal attention, one thread per q-row -------------------
// Block: 128 threads = 128 q rows. K/V tiles of 64 rows staged in smem.
// Online softmax with branch-on-new-max rescale (rare after warm-up).
__global__ __launch_bounds__(128)
void attn_kernel(const float* __restrict__ Qg, const float* __restrict__ Kg,
                 const float* __restrict__ Vg, float* __restrict__ Out)
{
    constexpr int TQ = 128, TK = 64;
    __shared__ float Ks[TK * HD];
    __shared__ float Vs[TK * HD];

    const int bh = blockIdx.y;            // 0..B*H-1
    const int b  = bh / HH;
    const int h  = bh % HH;
    const int q0 = blockIdx.x * TQ;
    const int tid = threadIdx.x;
    const int qi = q0 + tid;

    const float* Qrow = Qg + ((size_t)bh * LL + qi) * HD;
    float q[HD];
    #pragma unroll
    for (int d = 0; d < HD; d += 4) {
        float4 t = *(const float4*)(Qrow + d);
        q[d] = t.x; q[d + 1] = t.y; q[d + 2] = t.z; q[d + 3] = t.w;
    }

    float acc[HD];
    #pragma unroll
    for (int d = 0; d < HD; d++) acc[d] = 0.f;
    float m = -1e30f, lsum = 0.f;

    const int ntiles = q0 / TK + 2;       // covers keys [0, q0+127]
    const float4* Kb = (const float4*)(Kg + (size_t)bh * LL * HD);
    const float4* Vb = (const float4*)(Vg + (size_t)bh * LL * HD);

    for (int t = 0; t < ntiles; t++) {
        const int k0 = t * TK;
        __syncthreads();
        // stage K/V tile: 64x64 floats = 1024 float4 each
        {
            const float4* ksrc = Kb + (size_t)k0 * (HD / 4);
            const float4* vsrc = Vb + (size_t)k0 * (HD / 4);
            float4* kdst = (float4*)Ks;
            float4* vdst = (float4*)Vs;
            #pragma unroll
            for (int i = 0; i < (TK * HD / 4) / TQ; i++) {
                const int e = i * TQ + tid;
                kdst[e] = ksrc[e];
                vdst[e] = vsrc[e];
            }
        }
        __syncthreads();

        #pragma unroll 1
        for (int j = 0; j < TK; j++) {
            const float* kr = &Ks[j * HD];
            float s = 0.f;
            #pragma unroll
            for (int d = 0; d < HD; d += 4) {
                float4 kv = *(const float4*)(kr + d);
                s += q[d] * kv.x + q[d + 1] * kv.y + q[d + 2] * kv.z + q[d + 3] * kv.w;
            }
            if (k0 + j > qi) s = -1e30f;       // causal mask
            if (s > m) {                        // new running max (rare)
                const float corr = __expf(m - s);
                m = s;
                lsum *= corr;
                #pragma unroll
                for (int d = 0; d < HD; d++) acc[d] *= corr;
            }
            const float p = __expf(s - m);
            lsum += p;
            const float* vr = &Vs[j * HD];
            #pragma unroll
            for (int d = 0; d < HD; d += 4) {
                float4 vv = *(const float4*)(vr + d);
                acc[d]     += p * vv.x;
                acc[d + 1] += p * vv.y;
                acc[d + 2] += p * vv.z;
                acc[d + 3] += p * vv.w;
            }
        }
    }

    const float inv_l = 1.0f / lsum;
    // write to [B, L, H*HD]
    float* orow = Out + ((size_t)(b * LL + qi) * HH + h) * HD;
    #pragma unroll
    for (int d = 0; d < HD; d += 4) {
        float4 v;
        v.x = acc[d] * inv_l;     v.y = acc[d + 1] * inv_l;
        v.z = acc[d + 2] * inv_l; v.w = acc[d + 3] * inv_l;
        *(float4*)(orow + d) = v;
    }
}

// -------------------------------------------------------------------------
extern "C" void kernel_launch(void* const* d_in, const int* in_sizes, int n_in,
                              void* d_out, int out_size)
{
    const float* x        = (const float*)d_in[0];
    const float* rope_cos = (const float*)d_in[1];
    const float* rope_sin = (const float*)d_in[2];
    const float* W_qkv    = (const float*)d_in[3];
    const float* W_out    = (const float*)d_in[4];
    const float* b_out    = (const float*)d_in[5];
    float* out = (float*)d_out;

    float *qkv, *Q, *K, *V, *att;
    cudaGetSymbolAddress((void**)&qkv, g_qkv);
    cudaGetSymbolAddress((void**)&Q,   g_Q);
    cudaGetSymbolAddress((void**)&K,   g_K);
    cudaGetSymbolAddress((void**)&V,   g_V);
    cudaGetSymbolAddress((void**)&att, g_att);

    // 1) QKV projection: [4096,1024] @ [1024,3072]
    sgemm128<false><<<dim3(NQKV / 128, MROWS / 128), 256>>>(
        x, W_qkv, nullptr, qkv, MROWS, NQKV, DD);

    // 2) RoPE + reshape to [B,H,L,HD]
    {
        const int total = BB * LL * HH * 32;
        rope_reshape<<<total / 256, 256>>>(qkv, rope_cos, rope_sin, Q, K, V);
    }

    // 3) Causal attention -> [B,L,H*HD]
    attn_kernel<<<dim3(LL / 128, BB * HH), 128>>>(Q, K, V, att);

    // 4) Output projection + bias: [4096,1024] @ [1024,1024]
    sgemm128<true><<<dim3(DD / 128, MROWS / 128), 256>>>(
        att, W_out, b_out, out, MROWS, DD, DD);
}

// round 3
// speedup vs baseline: 1.3250x; 1.3250x over previous
#include <cuda_runtime.h>
#include <cuda_bf16.h>
#include <cstdint>

// Problem constants
#define BB 2
#define LL 2048
#define DD 1024
#define HH 16
#define HD 64
#define NQKV 3072        // 3*H*HD
#define MROWS (BB*LL)    // 4096

// ---------------- scratch (device globals; no allocations allowed) -------
__device__ float g_qkv[MROWS * NQKV];             // [B*L, 3072]
__device__ float g_Q[BB * HH * LL * HD];          // [B,H,L,HD] (rope'd, pre-scaled)
__device__ float g_K[BB * HH * LL * HD];          // [B,H,L,HD] (rope'd)
__device__ float g_V[BB * HH * LL * HD];          // [B,H,L,HD]
__device__ float g_att[MROWS * (HH * HD)];        // [B*L, 1024]

// split-bf16 operand buffers
__device__ __nv_bfloat16 g_xh[MROWS * DD];
__device__ __nv_bfloat16 g_xl[MROWS * DD];
__device__ __nv_bfloat16 g_wqkvT_h[NQKV * DD];    // [N][K]
__device__ __nv_bfloat16 g_wqkvT_l[NQKV * DD];
__device__ __nv_bfloat16 g_woutT_h[DD * DD];      // [N][K]
__device__ __nv_bfloat16 g_woutT_l[DD * DD];
__device__ __nv_bfloat16 g_atth[MROWS * DD];
__device__ __nv_bfloat16 g_attl[MROWS * DD];

// ==================== helpers =============================================
__device__ __forceinline__ uint32_t smem_u32(const void* p) {
    uint32_t a;
    asm("{ .reg .u64 t; cvta.to.shared.u64 t, %1; cvt.u32.u64 %0, t; }"
        : "=r"(a) : "l"(p));
    return a;
}

__device__ __forceinline__ void split1(float v, __nv_bfloat16& hi, __nv_bfloat16& lo) {
    hi = __float2bfloat16(v);
    lo = __float2bfloat16(v - __bfloat162float(hi));
}

__device__ __forceinline__ void ldsm4(uint32_t* r, uint32_t addr) {
    asm volatile("ldmatrix.sync.aligned.m8n8.x4.shared.b16 {%0,%1,%2,%3}, [%4];"
                 : "=r"(r[0]), "=r"(r[1]), "=r"(r[2]), "=r"(r[3]) : "r"(addr));
}

__device__ __forceinline__ void mma_bf16(float* d, const uint32_t* a, uint32_t b0, uint32_t b1) {
    asm volatile(
        "mma.sync.aligned.m16n8k16.row.col.f32.bf16.bf16.f32 "
        "{%0,%1,%2,%3}, {%4,%5,%6,%7}, {%8,%9}, {%0,%1,%2,%3};"
        : "+f"(d[0]), "+f"(d[1]), "+f"(d[2]), "+f"(d[3])
        : "r"(a[0]), "r"(a[1]), "r"(a[2]), "r"(a[3]), "r"(b0), "r"(b1));
}

// ==================== conversion kernels ==================================
// fp32 -> split bf16 (row-major preserved)
__global__ void conv_split(const float* __restrict__ src,
                           __nv_bfloat16* __restrict__ hi,
                           __nv_bfloat16* __restrict__ lo, int n4)
{
    const int i = blockIdx.x * blockDim.x + threadIdx.x;
    if (i >= n4) return;
    float4 v = ((const float4*)src)[i];
    __nv_bfloat16 h[4], l[4];
    split1(v.x, h[0], l[0]);
    split1(v.y, h[1], l[1]);
    split1(v.z, h[2], l[2]);
    split1(v.w, h[3], l[3]);
    ((uint2*)hi)[i] = *(uint2*)h;
    ((uint2*)lo)[i] = *(uint2*)l;
}

// W[K][N] fp32 -> hiT/loT [N][K] bf16 (transpose + split)
__global__ void conv_splitT(const float* __restrict__ W,
                            __nv_bfloat16* __restrict__ hiT,
                            __nv_bfloat16* __restrict__ loT,
                            int Kdim, int Ndim)
{
    __shared__ float t[32][33];
    const int tx = threadIdx.x, ty = threadIdx.y;
    const int nb = blockIdx.x * 32;
    const int kb = blockIdx.y * 32;
    #pragma unroll
    for (int i = 0; i < 4; i++)
        t[ty + i * 8][tx] = W[(size_t)(kb + ty + i * 8) * Ndim + nb + tx];
    __syncthreads();
    #pragma unroll
    for (int i = 0; i < 4; i++) {
        const float v = t[tx][ty + i * 8];     // = W[kb+tx][nb+ty+8i]
        __nv_bfloat16 h, l;
        split1(v, h, l);
        const size_t o = (size_t)(nb + ty + i * 8) * Kdim + kb + tx;
        hiT[o] = h;
        loT[o] = l;
    }
}

// ==================== warp-mma split-bf16 GEMM ============================
// C[M x Ntot] = A[M x K] @ B^T  where A given as Ah/Al [M][K] bf16,
// B given as Bh/Bl [Ntot][K] bf16. fp32 accumulate (+bias).
#define GBM 128
#define GBN 128
#define GBK 32                 // bf16 elems per chunk
#define SROW 20                // padded row stride (u32) = 80B -> LDSM conflict-free

template <bool BIAS>
__global__ __launch_bounds__(256, 2)
void mma_gemm(const __nv_bfloat16* __restrict__ Ahg, const __nv_bfloat16* __restrict__ Alg,
              const __nv_bfloat16* __restrict__ Bhg, const __nv_bfloat16* __restrict__ Blg,
              const float* __restrict__ bias, float* __restrict__ C,
              int M, int Ntot, int K)
{
    __shared__ uint32_t sAh[GBM * SROW], sAl[GBM * SROW];
    __shared__ uint32_t sBh[GBN * SROW], sBl[GBN * SROW];

    const int tid = threadIdx.x;
    const int wid = tid >> 5;
    const int lane = tid & 31;
    const int warpM = wid & 3;          // 4 warps in M
    const int warpN = wid >> 2;         // 2 warps in N
    const int mBase = blockIdx.y * GBM;
    const int nBase = blockIdx.x * GBN;

    const uint32_t bAh = smem_u32(sAh), bAl = smem_u32(sAl);
    const uint32_t bBh = smem_u32(sBh), bBl = smem_u32(sBl);

    // ldmatrix lane address within a tile buffer (byte offset)
    const uint32_t lrow = lane & 15;
    const uint32_t lhi  = (lane >> 4) << 4;     // +16B for k-high half

    float acc[2][8][4];
    #pragma unroll
    for (int a = 0; a < 2; a++)
        #pragma unroll
        for (int b = 0; b < 8; b++)
            #pragma unroll
            for (int c2 = 0; c2 < 4; c2++) acc[a][b][c2] = 0.f;

    const int row = tid >> 1;          // 0..127
    const int seg = tid & 1;           // 16 bf16 halves
    const int nchunks = K / GBK;

    for (int c = 0; c < nchunks; c++) {
        const int k0 = c * GBK;
        __syncthreads();
        // ---- stage A (128 x 32 bf16, hi+lo) ----
        {
            const size_t g = (size_t)(mBase + row) * K + k0 + seg * 16;
            const uint4* ph = (const uint4*)(Ahg + g);
            const uint4* pl = (const uint4*)(Alg + g);
            const uint32_t so = row * SROW + seg * 8;
            *(uint4*)&sAh[so]     = ph[0];
            *(uint4*)&sAh[so + 4] = ph[1];
            *(uint4*)&sAl[so]     = pl[0];
            *(uint4*)&sAl[so + 4] = pl[1];
        }
        // ---- stage B (128 n x 32 k bf16, hi+lo) ----
        {
            const size_t g = (size_t)(nBase + row) * K + k0 + seg * 16;
            const uint4* ph = (const uint4*)(Bhg + g);
            const uint4* pl = (const uint4*)(Blg + g);
            const uint32_t so = row * SROW + seg * 8;
            *(uint4*)&sBh[so]     = ph[0];
            *(uint4*)&sBh[so + 4] = ph[1];
            *(uint4*)&sBl[so]     = pl[0];
            *(uint4*)&sBl[so + 4] = pl[1];
        }
        __syncthreads();

        #pragma unroll
        for (int ks = 0; ks < 2; ks++) {
            const uint32_t kboff = ks * 32 + lhi;   // byte offset for this lane
            // A fragments (2 m-tiles, hi+lo)
            uint32_t ah[2][4], al[2][4];
            #pragma unroll
            for (int mt = 0; mt < 2; mt++) {
                const uint32_t ro = (warpM * 32 + mt * 16 + lrow) * (SROW * 4) + kboff;
                ldsm4(ah[mt], bAh + ro);
                ldsm4(al[mt], bAl + ro);
            }
            // B regions (4 x n16), hi+lo
            #pragma unroll
            for (int reg = 0; reg < 4; reg++) {
                const uint32_t ro = (warpN * 64 + reg * 16 + lrow) * (SROW * 4) + kboff;
                uint32_t bh[4], bl[4];
                ldsm4(bh, bBh + ro);
                ldsm4(bl, bBl + ro);
                #pragma unroll
                for (int mt = 0; mt < 2; mt++) {
                    #pragma unroll
                    for (int t = 0; t < 2; t++) {
                        float* d = acc[mt][reg * 2 + t];
                        mma_bf16(d, ah[mt], bh[t], bh[t + 2]);   // Ah*Bh
                        mma_bf16(d, ah[mt], bl[t], bl[t + 2]);   // Ah*Bl
                        mma_bf16(d, al[mt], bh[t], bh[t + 2]);   // Al*Bh
                    }
                }
            }
        }
    }

    // ---- epilogue ----
    const int qrow = lane >> 2;
    const int qcol = (lane & 3) * 2;
    #pragma unroll
    for (int mt = 0; mt < 2; mt++) {
        const int m0 = mBase + warpM * 32 + mt * 16 + qrow;
        #pragma unroll
        for (int n8 = 0; n8 < 8; n8++) {
            const int col = nBase + warpN * 64 + n8 * 8 + qcol;
            float2 v0, v1;
            v0.x = acc[mt][n8][0]; v0.y = acc[mt][n8][1];
            v1.x = acc[mt][n8][2]; v1.y = acc[mt][n8][3];
            if (BIAS) {
                const float b0 = bias[col], b1 = bias[col + 1];
                v0.x += b0; v0.y += b1;
                v1.x += b0; v1.y += b1;
            }
            *(float2*)&C[(size_t)m0 * Ntot + col] = v0;
            *(float2*)&C[(size_t)(m0 + 8) * Ntot + col] = v1;
        }
    }
}

// --------------- RoPE + reshape [B,L,3*H*HD] -> Q/K/V [B,H,L,HD] ----------
__global__ void rope_reshape(const float* __restrict__ qkv,
                             const float* __restrict__ cosT,
                             const float* __restrict__ sinT,
                             float* __restrict__ Qo, float* __restrict__ Ko,
                             float* __restrict__ Vo)
{
    const int idx = blockIdx.x * blockDim.x + threadIdx.x;
    if (idx >= BB * LL * HH * 32) return;
    const int d = idx & 31;
    const int h = (idx >> 5) & (HH - 1);
    const int l = (idx >> 9) & (LL - 1);
    const int b = idx >> 20;

    const float* row = qkv + ((size_t)(b * LL + l)) * NQKV;
    const float c0 = cosT[l * HD + d],      c1 = cosT[l * HD + d + 32];
    const float s0 = sinT[l * HD + d],      s1 = sinT[l * HD + d + 32];

    const float q0 = row[h * HD + d],            q1 = row[h * HD + d + 32];
    const float k0 = row[DD + h * HD + d],       k1 = row[DD + h * HD + d + 32];
    const float v0 = row[2 * DD + h * HD + d],   v1 = row[2 * DD + h * HD + d + 32];

    const float scale = 0.125f;   // 64^-0.5
    const size_t o = ((size_t)(b * HH + h) * LL + l) * HD;
    Qo[o + d]      = (q0 * c0 - q1 * s0) * scale;
    Qo[o + d + 32] = (q1 * c1 + q0 * s1) * scale;
    Ko[o + d]      = k0 * c0 - k1 * s0;
    Ko[o + d + 32] = k1 * c1 + k0 * s1;
    Vo[o + d]      = v0;
    Vo[o + d + 32] = v1;
}

// --------------- Causal attention, one thread per q-row -------------------
__global__ __launch_bounds__(128)
void attn_kernel(const float* __restrict__ Qg, const float* __restrict__ Kg,
                 const float* __restrict__ Vg, float* __restrict__ Out)
{
    constexpr int TQ = 128, TK = 64;
    __shared__ float Ks[TK * HD];
    __shared__ float Vs[TK * HD];

    const int bh = blockIdx.y;
    const int b  = bh / HH;
    const int h  = bh % HH;
    const int q0 = blockIdx.x * TQ;
    const int tid = threadIdx.x;
    const int qi = q0 + tid;

    const float* Qrow = Qg + ((size_t)bh * LL + qi) * HD;
    float q[HD];
    #pragma unroll
    for (int d = 0; d < HD; d += 4) {
        float4 t = *(const float4*)(Qrow + d);
        q[d] = t.x; q[d + 1] = t.y; q[d + 2] = t.z; q[d + 3] = t.w;
    }

    float acc[HD];
    #pragma unroll
    for (int d = 0; d < HD; d++) acc[d] = 0.f;
    float m = -1e30f, lsum = 0.f;

    const int ntiles = q0 / TK + 2;
    const float4* Kb = (const float4*)(Kg + (size_t)bh * LL * HD);
    const float4* Vb = (const float4*)(Vg + (size_t)bh * LL * HD);

    for (int t = 0; t < ntiles; t++) {
        const int k0 = t * TK;
        __syncthreads();
        {
            const float4* ksrc = Kb + (size_t)k0 * (HD / 4);
            const float4* vsrc = Vb + (size_t)k0 * (HD / 4);
            float4* kdst = (float4*)Ks;
            float4* vdst = (float4*)Vs;
            #pragma unroll
            for (int i = 0; i < (TK * HD / 4) / TQ; i++) {
                const int e = i * TQ + tid;
                kdst[e] = ksrc[e];
                vdst[e] = vsrc[e];
            }
        }
        __syncthreads();

        #pragma unroll 1
        for (int j = 0; j < TK; j++) {
            const float* kr = &Ks[j * HD];
            float s = 0.f;
            #pragma unroll
            for (int d = 0; d < HD; d += 4) {
                float4 kv = *(const float4*)(kr + d);
                s += q[d] * kv.x + q[d + 1] * kv.y + q[d + 2] * kv.z + q[d + 3] * kv.w;
            }
            if (k0 + j > qi) s = -1e30f;
            if (s > m) {
                const float corr = __expf(m - s);
                m = s;
                lsum *= corr;
                #pragma unroll
                for (int d = 0; d < HD; d++) acc[d] *= corr;
            }
            const float p = __expf(s - m);
            lsum += p;
            const float* vr = &Vs[j * HD];
            #pragma unroll
            for (int d = 0; d < HD; d += 4) {
                float4 vv = *(const float4*)(vr + d);
                acc[d]     += p * vv.x;
                acc[d + 1] += p * vv.y;
                acc[d + 2] += p * vv.z;
                acc[d + 3] += p * vv.w;
            }
        }
    }

    const float inv_l = 1.0f / lsum;
    float* orow = Out + ((size_t)(b * LL + qi) * HH + h) * HD;
    #pragma unroll
    for (int d = 0; d < HD; d += 4) {
        float4 v;
        v.x = acc[d] * inv_l;     v.y = acc[d + 1] * inv_l;
        v.z = acc[d + 2] * inv_l; v.w = acc[d + 3] * inv_l;
        *(float4*)(orow + d) = v;
    }
}

// -------------------------------------------------------------------------
extern "C" void kernel_launch(void* const* d_in, const int* in_sizes, int n_in,
                              void* d_out, int out_size)
{
    const float* x        = (const float*)d_in[0];
    const float* rope_cos = (const float*)d_in[1];
    const float* rope_sin = (const float*)d_in[2];
    const float* W_qkv    = (const float*)d_in[3];
    const float* W_out    = (const float*)d_in[4];
    const float* b_out    = (const float*)d_in[5];
    float* out = (float*)d_out;

    float *qkv, *Q, *K, *V, *att;
    cudaGetSymbolAddress((void**)&qkv, g_qkv);
    cudaGetSymbolAddress((void**)&Q,   g_Q);
    cudaGetSymbolAddress((void**)&K,   g_K);
    cudaGetSymbolAddress((void**)&V,   g_V);
    cudaGetSymbolAddress((void**)&att, g_att);

    __nv_bfloat16 *xh, *xl, *wqh, *wql, *woh, *wol, *ath, *atl;
    cudaGetSymbolAddress((void**)&xh,  g_xh);
    cudaGetSymbolAddress((void**)&xl,  g_xl);
    cudaGetSymbolAddress((void**)&wqh, g_wqkvT_h);
    cudaGetSymbolAddress((void**)&wql, g_wqkvT_l);
    cudaGetSymbolAddress((void**)&woh, g_woutT_h);
    cudaGetSymbolAddress((void**)&wol, g_woutT_l);
    cudaGetSymbolAddress((void**)&ath, g_atth);
    cudaGetSymbolAddress((void**)&atl, g_attl);

    // 0) operand conversion
    conv_split<<<(MROWS * DD / 4 + 255) / 256, 256>>>(x, xh, xl, MROWS * DD / 4);
    conv_splitT<<<dim3(NQKV / 32, DD / 32), dim3(32, 8)>>>(W_qkv, wqh, wql, DD, NQKV);
    conv_splitT<<<dim3(DD / 32, DD / 32),   dim3(32, 8)>>>(W_out, woh, wol, DD, DD);

    // 1) QKV projection on tensor cores (split bf16, 3-term)
    mma_gemm<false><<<dim3(NQKV / GBN, MROWS / GBM), 256>>>(
        xh, xl, wqh, wql, nullptr, qkv, MROWS, NQKV, DD);

    // 2) RoPE + reshape to [B,H,L,HD]
    {
        const int total = BB * LL * HH * 32;
        rope_reshape<<<total / 256, 256>>>(qkv, rope_cos, rope_sin, Q, K, V);
    }

    // 3) Causal attention -> [B,L,H*HD]
    attn_kernel<<<dim3(LL / 128, BB * HH), 128>>>(Q, K, V, att);

    // 4) split-convert attention output, then output projection + bias
    conv_split<<<(MROWS * DD / 4 + 255) / 256, 256>>>(att, ath, atl, MROWS * DD / 4);
    mma_gemm<true><<<dim3(DD / GBN, MROWS / GBM), 256>>>(
        ath, atl, woh, wol, b_out, out, MROWS, DD, DD);
}

// round 4
// speedup vs baseline: 2.6474x; 1.9980x over previous
#include <cuda_runtime.h>
#include <cuda_bf16.h>
#include <cstdint>

// Problem constants
#define BB 2
#define LL 2048
#define DD 1024
#define HH 16
#define HD 64
#define NQKV 3072        // 3*H*HD
#define MROWS (BB*LL)    // 4096

// ---------------- scratch (device globals; no allocations allowed) -------
__device__ float g_qkv[MROWS * NQKV];             // [B*L, 3072] fp32

// split-bf16 operand buffers
__device__ __nv_bfloat16 g_xh[MROWS * DD];
__device__ __nv_bfloat16 g_xl[MROWS * DD];
__device__ __nv_bfloat16 g_wqkvT_h[NQKV * DD];    // [N][K]
__device__ __nv_bfloat16 g_wqkvT_l[NQKV * DD];
__device__ __nv_bfloat16 g_woutT_h[DD * DD];      // [N][K]
__device__ __nv_bfloat16 g_woutT_l[DD * DD];

// attention operands/results, split bf16, [B,H,L,HD] (Q scaled by 0.125*log2e)
__device__ __nv_bfloat16 g_Qh[BB * HH * LL * HD];
__device__ __nv_bfloat16 g_Ql[BB * HH * LL * HD];
__device__ __nv_bfloat16 g_Kh[BB * HH * LL * HD];
__device__ __nv_bfloat16 g_Kl[BB * HH * LL * HD];
__device__ __nv_bfloat16 g_Vh[BB * HH * LL * HD];
__device__ __nv_bfloat16 g_Vl[BB * HH * LL * HD];
__device__ __nv_bfloat16 g_atth[MROWS * DD];      // [B*L, 1024]
__device__ __nv_bfloat16 g_attl[MROWS * DD];

// ==================== helpers =============================================
__device__ __forceinline__ uint32_t smem_u32(const void* p) {
    uint32_t a;
    asm("{ .reg .u64 t; cvta.to.shared.u64 t, %1; cvt.u32.u64 %0, t; }"
        : "=r"(a) : "l"(p));
    return a;
}

__device__ __forceinline__ void split1(float v, __nv_bfloat16& hi, __nv_bfloat16& lo) {
    hi = __float2bfloat16(v);
    lo = __float2bfloat16(v - __bfloat162float(hi));
}

// pack (lo_elem, hi_elem) floats -> bf16x2 reg (lo in bits[15:0])
__device__ __forceinline__ uint32_t packbf(float lo, float hi) {
    uint32_t r;
    asm("cvt.rn.bf16x2.f32 %0, %1, %2;" : "=r"(r) : "f"(hi), "f"(lo));
    return r;
}

// split two floats into hi-pair and lo-pair bf16x2 regs
__device__ __forceinline__ void split_pack(float a, float b, uint32_t& hi, uint32_t& lo) {
    __nv_bfloat16 ah = __float2bfloat16(a), bh = __float2bfloat16(b);
    hi = (uint32_t)__bfloat16_as_ushort(ah) | ((uint32_t)__bfloat16_as_ushort(bh) << 16);
    lo = packbf(a - __bfloat162float(ah), b - __bfloat162float(bh));
}

__device__ __forceinline__ void ldsm4(uint32_t* r, uint32_t addr) {
    asm volatile("ldmatrix.sync.aligned.m8n8.x4.shared.b16 {%0,%1,%2,%3}, [%4];"
                 : "=r"(r[0]), "=r"(r[1]), "=r"(r[2]), "=r"(r[3]) : "r"(addr));
}

__device__ __forceinline__ void ldsm4t(uint32_t* r, uint32_t addr) {
    asm volatile("ldmatrix.sync.aligned.m8n8.x4.trans.shared.b16 {%0,%1,%2,%3}, [%4];"
                 : "=r"(r[0]), "=r"(r[1]), "=r"(r[2]), "=r"(r[3]) : "r"(addr));
}

__device__ __forceinline__ void mma_bf16(float* d, const uint32_t* a, uint32_t b0, uint32_t b1) {
    asm volatile(
        "mma.sync.aligned.m16n8k16.row.col.f32.bf16.bf16.f32 "
        "{%0,%1,%2,%3}, {%4,%5,%6,%7}, {%8,%9}, {%0,%1,%2,%3};"
        : "+f"(d[0]), "+f"(d[1]), "+f"(d[2]), "+f"(d[3])
        : "r"(a[0]), "r"(a[1]), "r"(a[2]), "r"(a[3]), "r"(b0), "r"(b1));
}

// fast exp2 on FMA pipe (x <= 0 expected; clamped at -120)
__device__ __forceinline__ float fexp2(float x) {
    x = fmaxf(x, -120.0f);
    float n = floorf(x);
    float f = x - n;
    float p = 1.5404226e-4f;
    p = fmaf(p, f, 1.3333558e-3f);
    p = fmaf(p, f, 9.6181291e-3f);
    p = fmaf(p, f, 5.5504109e-2f);
    p = fmaf(p, f, 2.4022651e-1f);
    p = fmaf(p, f, 6.9314718e-1f);
    p = fmaf(p, f, 1.0f);
    return __int_as_float(__float_as_int(p) + (((int)n) << 23));
}

// ==================== conversion kernels ==================================
__global__ void conv_split(const float* __restrict__ src,
                           __nv_bfloat16* __restrict__ hi,
                           __nv_bfloat16* __restrict__ lo, int n4)
{
    const int i = blockIdx.x * blockDim.x + threadIdx.x;
    if (i >= n4) return;
    float4 v = ((const float4*)src)[i];
    __nv_bfloat16 h[4], l[4];
    split1(v.x, h[0], l[0]);
    split1(v.y, h[1], l[1]);
    split1(v.z, h[2], l[2]);
    split1(v.w, h[3], l[3]);
    ((uint2*)hi)[i] = *(uint2*)h;
    ((uint2*)lo)[i] = *(uint2*)l;
}

__global__ void conv_splitT(const float* __restrict__ W,
                            __nv_bfloat16* __restrict__ hiT,
                            __nv_bfloat16* __restrict__ loT,
                            int Kdim, int Ndim)
{
    __shared__ float t[32][33];
    const int tx = threadIdx.x, ty = threadIdx.y;
    const int nb = blockIdx.x * 32;
    const int kb = blockIdx.y * 32;
    #pragma unroll
    for (int i = 0; i < 4; i++)
        t[ty + i * 8][tx] = W[(size_t)(kb + ty + i * 8) * Ndim + nb + tx];
    __syncthreads();
    #pragma unroll
    for (int i = 0; i < 4; i++) {
        const float v = t[tx][ty + i * 8];
        __nv_bfloat16 h, l;
        split1(v, h, l);
        const size_t o = (size_t)(nb + ty + i * 8) * Kdim + kb + tx;
        hiT[o] = h;
        loT[o] = l;
    }
}

// ==================== warp-mma split-bf16 GEMM ============================
#define GBM 128
#define GBN 128
#define GBK 32
#define SROW 20

template <bool BIAS>
__global__ __launch_bounds__(256, 2)
void mma_gemm(const __nv_bfloat16* __restrict__ Ahg, const __nv_bfloat16* __restrict__ Alg,
              const __nv_bfloat16* __restrict__ Bhg, const __nv_bfloat16* __restrict__ Blg,
              const float* __restrict__ bias, float* __restrict__ C,
              int M, int Ntot, int K)
{
    __shared__ uint32_t sAh[GBM * SROW], sAl[GBM * SROW];
    __shared__ uint32_t sBh[GBN * SROW], sBl[GBN * SROW];

    const int tid = threadIdx.x;
    const int wid = tid >> 5;
    const int lane = tid & 31;
    const int warpM = wid & 3;
    const int warpN = wid >> 2;
    const int mBase = blockIdx.y * GBM;
    const int nBase = blockIdx.x * GBN;

    const uint32_t bAh = smem_u32(sAh), bAl = smem_u32(sAl);
    const uint32_t bBh = smem_u32(sBh), bBl = smem_u32(sBl);

    const uint32_t lrow = lane & 15;
    const uint32_t lhi  = (lane >> 4) << 4;

    float acc[2][8][4];
    #pragma unroll
    for (int a = 0; a < 2; a++)
        #pragma unroll
        for (int b = 0; b < 8; b++)
            #pragma unroll
            for (int c2 = 0; c2 < 4; c2++) acc[a][b][c2] = 0.f;

    const int row = tid >> 1;
    const int seg = tid & 1;
    const int nchunks = K / GBK;

    for (int c = 0; c < nchunks; c++) {
        const int k0 = c * GBK;
        __syncthreads();
        {
            const size_t g = (size_t)(mBase + row) * K + k0 + seg * 16;
            const uint4* ph = (const uint4*)(Ahg + g);
            const uint4* pl = (const uint4*)(Alg + g);
            const uint32_t so = row * SROW + seg * 8;
            *(uint4*)&sAh[so]     = ph[0];
            *(uint4*)&sAh[so + 4] = ph[1];
            *(uint4*)&sAl[so]     = pl[0];
            *(uint4*)&sAl[so + 4] = pl[1];
        }
        {
            const size_t g = (size_t)(nBase + row) * K + k0 + seg * 16;
            const uint4* ph = (const uint4*)(Bhg + g);
            const uint4* pl = (const uint4*)(Blg + g);
            const uint32_t so = row * SROW + seg * 8;
            *(uint4*)&sBh[so]     = ph[0];
            *(uint4*)&sBh[so + 4] = ph[1];
            *(uint4*)&sBl[so]     = pl[0];
            *(uint4*)&sBl[so + 4] = pl[1];
        }
        __syncthreads();

        #pragma unroll
        for (int ks = 0; ks < 2; ks++) {
            const uint32_t kboff = ks * 32 + lhi;
            uint32_t ah[2][4], al[2][4];
            #pragma unroll
            for (int mt = 0; mt < 2; mt++) {
                const uint32_t ro = (warpM * 32 + mt * 16 + lrow) * (SROW * 4) + kboff;
                ldsm4(ah[mt], bAh + ro);
                ldsm4(al[mt], bAl + ro);
            }
            #pragma unroll
            for (int reg = 0; reg < 4; reg++) {
                const uint32_t ro = (warpN * 64 + reg * 16 + lrow) * (SROW * 4) + kboff;
                uint32_t bh[4], bl[4];
                ldsm4(bh, bBh + ro);
                ldsm4(bl, bBl + ro);
                #pragma unroll
                for (int mt = 0; mt < 2; mt++) {
                    #pragma unroll
                    for (int t = 0; t < 2; t++) {
                        float* d = acc[mt][reg * 2 + t];
                        mma_bf16(d, ah[mt], bh[t], bh[t + 2]);
                        mma_bf16(d, ah[mt], bl[t], bl[t + 2]);
                        mma_bf16(d, al[mt], bh[t], bh[t + 2]);
                    }
                }
            }
        }
    }

    const int qrow = lane >> 2;
    const int qcol = (lane & 3) * 2;
    #pragma unroll
    for (int mt = 0; mt < 2; mt++) {
        const int m0 = mBase + warpM * 32 + mt * 16 + qrow;
        #pragma unroll
        for (int n8 = 0; n8 < 8; n8++) {
            const int col = nBase + warpN * 64 + n8 * 8 + qcol;
            float2 v0, v1;
            v0.x = acc[mt][n8][0]; v0.y = acc[mt][n8][1];
            v1.x = acc[mt][n8][2]; v1.y = acc[mt][n8][3];
            if (BIAS) {
                const float b0 = bias[col], b1 = bias[col + 1];
                v0.x += b0; v0.y += b1;
                v1.x += b0; v1.y += b1;
            }
            *(float2*)&C[(size_t)m0 * Ntot + col] = v0;
            *(float2*)&C[(size_t)(m0 + 8) * Ntot + col] = v1;
        }
    }
}

// --------------- RoPE + reshape + split to bf16 ---------------------------
// qkv [B,L,3072] fp32 -> Qh/Ql (scaled by 0.125*log2(e)), Kh/Kl, Vh/Vl
// in [B,H,L,HD] bf16 split pairs.
__global__ void rope_split(const float* __restrict__ qkv,
                           const float* __restrict__ cosT,
                           const float* __restrict__ sinT,
                           __nv_bfloat16* __restrict__ Qh, __nv_bfloat16* __restrict__ Ql,
                           __nv_bfloat16* __restrict__ Kh, __nv_bfloat16* __restrict__ Kl,
                           __nv_bfloat16* __restrict__ Vh, __nv_bfloat16* __restrict__ Vl)
{
    const int idx = blockIdx.x * blockDim.x + threadIdx.x;
    if (idx >= BB * LL * HH * 32) return;
    const int d = idx & 31;
    const int h = (idx >> 5) & (HH - 1);
    const int l = (idx >> 9) & (LL - 1);
    const int b = idx >> 20;

    const float* row = qkv + ((size_t)(b * LL + l)) * NQKV;
    const float c0 = cosT[l * HD + d],      c1 = cosT[l * HD + d + 32];
    const float s0 = sinT[l * HD + d],      s1 = sinT[l * HD + d + 32];

    const float q0 = row[h * HD + d],            q1 = row[h * HD + d + 32];
    const float k0 = row[DD + h * HD + d],       k1 = row[DD + h * HD + d + 32];
    const float v0 = row[2 * DD + h * HD + d],   v1 = row[2 * DD + h * HD + d + 32];

    const float scale = 0.125f * 1.4426950408889634f;  // HD^-0.5 * log2(e)
    const size_t o = ((size_t)(b * HH + h) * LL + l) * HD;

    __nv_bfloat16 hi, lo;
    split1((q0 * c0 - q1 * s0) * scale, hi, lo); Qh[o + d] = hi;      Ql[o + d] = lo;
    split1((q1 * c1 + q0 * s1) * scale, hi, lo); Qh[o + d + 32] = hi; Ql[o + d + 32] = lo;
    split1(k0 * c0 - k1 * s0, hi, lo);           Kh[o + d] = hi;      Kl[o + d] = lo;
    split1(k1 * c1 + k0 * s1, hi, lo);           Kh[o + d + 32] = hi; Kl[o + d + 32] = lo;
    split1(v0, hi, lo);                          Vh[o + d] = hi;      Vl[o + d] = lo;
    split1(v1, hi, lo);                          Vh[o + d + 32] = hi; Vl[o + d + 32] = lo;
}

// --------------- flash attention (mma.sync, split bf16) -------------------
// Q tile 128 rows, 8 warps (16 rows each), K/V tiles of 64 keys.
// S = Q Kᵀ (3 split terms); softmax in log2 domain; O += P V (3 split terms).
#define RSTRIDE 144               // padded smem row (72 bf16)
#define ASQH 0
#define ASQL 18432
#define ASKH 36864
#define ASKL 46080
#define ASVH 55296
#define ASVL 64512
#define ATT_SMEM 73728

__global__ __launch_bounds__(256, 1)
void flash_attn(const __nv_bfloat16* __restrict__ Qhg, const __nv_bfloat16* __restrict__ Qlg,
                const __nv_bfloat16* __restrict__ Khg, const __nv_bfloat16* __restrict__ Klg,
                const __nv_bfloat16* __restrict__ Vhg, const __nv_bfloat16* __restrict__ Vlg,
                __nv_bfloat16* __restrict__ Oh, __nv_bfloat16* __restrict__ Ol)
{
    extern __shared__ char smem[];
    const uint32_t sb = smem_u32(smem);
    const int tid = threadIdx.x, wid = tid >> 5, lane = tid & 31;
    const int qt = (LL / 128 - 1) - blockIdx.x;     // big tiles first
    const int bh = blockIdx.y;
    const int b = bh >> 4, h = bh & 15;
    const int q0 = qt * 128;
    const size_t base = (size_t)bh * LL * HD;

    // ---- stage Q tile (hi & lo), 128 rows x 128B each ----
    {
        const int row = tid >> 1, seg = tid & 1;
        const uint4* gh = (const uint4*)(Qhg + base + (size_t)(q0 + row) * HD) + seg * 4;
        const uint4* gl = (const uint4*)(Qlg + base + (size_t)(q0 + row) * HD) + seg * 4;
        char* dh = smem + ASQH + row * RSTRIDE + seg * 64;
        char* dl = smem + ASQL + row * RSTRIDE + seg * 64;
        #pragma unroll
        for (int i = 0; i < 4; i++) {
            ((uint4*)dh)[i] = gh[i];
            ((uint4*)dl)[i] = gl[i];
        }
    }
    __syncthreads();

    // ---- Q fragments (persistent) ----
    uint32_t qh[4][4], ql[4][4];
    {
        const uint32_t ro = (wid * 16 + (lane & 15)) * RSTRIDE + ((lane >> 4) << 4);
        #pragma unroll
        for (int ks = 0; ks < 4; ks++) {
            ldsm4(qh[ks], sb + ASQH + ro + ks * 32);
            ldsm4(ql[ks], sb + ASQL + ro + ks * 32);
        }
    }

    float acc_o[8][4];
    #pragma unroll
    for (int j = 0; j < 8; j++)
        #pragma unroll
        for (int e = 0; e < 4; e++) acc_o[j][e] = 0.f;
    float m0 = -1e30f, m1 = -1e30f, l0 = 0.f, l1 = 0.f;

    const int qmin = q0 + wid * 16;
    const int r_lo = qmin + (lane >> 2);           // global row of acc elems 0,1
    const int ntiles = q0 / 64 + 2;

    for (int t = 0; t < ntiles; t++) {
        const int k0 = t * 64;
        __syncthreads();
        // ---- stage K/V tiles (hi & lo): 64 rows x 128B each ----
        #pragma unroll
        for (int j = 0; j < 2; j++) {
            const int item = j * 256 + tid;        // 0..511
            const int row = item >> 3, seg = item & 7;
            const size_t g = base + (size_t)(k0 + row) * HD + seg * 8;
            const uint32_t so = row * RSTRIDE + seg * 16;
            *(uint4*)(smem + ASKH + so) = *(const uint4*)(Khg + g);
            *(uint4*)(smem + ASKL + so) = *(const uint4*)(Klg + g);
            *(uint4*)(smem + ASVH + so) = *(const uint4*)(Vhg + g);
            *(uint4*)(smem + ASVL + so) = *(const uint4*)(Vlg + g);
        }
        __syncthreads();

        if (k0 > qmin + 15) continue;              // fully masked for this warp

        // ---- S = Q·Kᵀ ----
        float s[8][4];
        #pragma unroll
        for (int j = 0; j < 8; j++)
            #pragma unroll
            for (int e = 0; e < 4; e++) s[j][e] = 0.f;

        #pragma unroll
        for (int ks = 0; ks < 4; ks++) {
            #pragma unroll
            for (int np = 0; np < 4; np++) {
                uint32_t kh[4], kl[4];
                const uint32_t ro = (np * 16 + (lane & 15)) * RSTRIDE +
                                    ((lane >> 4) << 4) + ks * 32;
                ldsm4(kh, sb + ASKH + ro);
                ldsm4(kl, sb + ASKL + ro);
                mma_bf16(s[2 * np],     qh[ks], kh[0], kh[2]);
                mma_bf16(s[2 * np],     qh[ks], kl[0], kl[2]);
                mma_bf16(s[2 * np],     ql[ks], kh[0], kh[2]);
                mma_bf16(s[2 * np + 1], qh[ks], kh[1], kh[3]);
                mma_bf16(s[2 * np + 1], qh[ks], kl[1], kl[3]);
                mma_bf16(s[2 * np + 1], ql[ks], kh[1], kh[3]);
            }
        }

        // ---- causal mask (only near-diagonal tiles) ----
        if (k0 + 63 > qmin) {
            #pragma unroll
            for (int j = 0; j < 8; j++) {
                const int key = k0 + j * 8 + (lane & 3) * 2;
                if (key     > r_lo)     s[j][0] = -1e30f;
                if (key + 1 > r_lo)     s[j][1] = -1e30f;
                if (key     > r_lo + 8) s[j][2] = -1e30f;
                if (key + 1 > r_lo + 8) s[j][3] = -1e30f;
            }
        }

        // ---- online softmax (log2 domain) ----
        float rm0 = -1e30f, rm1 = -1e30f;
        #pragma unroll
        for (int j = 0; j < 8; j++) {
            rm0 = fmaxf(rm0, fmaxf(s[j][0], s[j][1]));
            rm1 = fmaxf(rm1, fmaxf(s[j][2], s[j][3]));
        }
        rm0 = fmaxf(rm0, __shfl_xor_sync(0xffffffff, rm0, 1));
        rm0 = fmaxf(rm0, __shfl_xor_sync(0xffffffff, rm0, 2));
        rm1 = fmaxf(rm1, __shfl_xor_sync(0xffffffff, rm1, 1));
        rm1 = fmaxf(rm1, __shfl_xor_sync(0xffffffff, rm1, 2));

        const float mn0 = fmaxf(m0, rm0), mn1 = fmaxf(m1, rm1);
        const float c0 = fexp2(m0 - mn0), c1 = fexp2(m1 - mn1);
        m0 = mn0; m1 = mn1;
        l0 *= c0; l1 *= c1;
        #pragma unroll
        for (int j = 0; j < 8; j++) {
            acc_o[j][0] *= c0; acc_o[j][1] *= c0;
            acc_o[j][2] *= c1; acc_o[j][3] *= c1;
        }

        float p[8][4];
        #pragma unroll
        for (int j = 0; j < 8; j++) {
            p[j][0] = fexp2(s[j][0] - m0);
            p[j][1] = fexp2(s[j][1] - m0);
            p[j][2] = fexp2(s[j][2] - m1);
            p[j][3] = fexp2(s[j][3] - m1);
            l0 += p[j][0] + p[j][1];
            l1 += p[j][2] + p[j][3];
        }

        // ---- pack P into A-fragments (hi & lo) ----
        uint32_t pha[4][4], pla[4][4];
        #pragma unroll
        for (int ks = 0; ks < 4; ks++) {
            const int j0 = 2 * ks, j1 = 2 * ks + 1;
            split_pack(p[j0][0], p[j0][1], pha[ks][0], pla[ks][0]);
            split_pack(p[j0][2], p[j0][3], pha[ks][1], pla[ks][1]);
            split_pack(p[j1][0], p[j1][1], pha[ks][2], pla[ks][2]);
            split_pack(p[j1][2], p[j1][3], pha[ks][3], pla[ks][3]);
        }

        // ---- O += P·V ----
        #pragma unroll
        for (int ks = 0; ks < 4; ks++) {
            #pragma unroll
            for (int np = 0; np < 4; np++) {
                uint32_t vh[4], vl[4];
                const int g = lane >> 3;
                const uint32_t row = ks * 16 + (g & 1) * 8 + (lane & 7);
                const uint32_t ro = row * RSTRIDE + np * 32 + (g >> 1) * 16;
                ldsm4t(vh, sb + ASVH + ro);
                ldsm4t(vl, sb + ASVL + ro);
                mma_bf16(acc_o[2 * np],     pha[ks], vh[0], vh[1]);
                mma_bf16(acc_o[2 * np],     pha[ks], vl[0], vl[1]);
                mma_bf16(acc_o[2 * np],     pla[ks], vh[0], vh[1]);
                mma_bf16(acc_o[2 * np + 1], pha[ks], vh[2], vh[3]);
                mma_bf16(acc_o[2 * np + 1], pha[ks], vl[2], vl[3]);
                mma_bf16(acc_o[2 * np + 1], pla[ks], vh[2], vh[3]);
            }
        }
    }

    // ---- epilogue: normalize, split, write [B*L, 1024] ----
    l0 += __shfl_xor_sync(0xffffffff, l0, 1);
    l0 += __shfl_xor_sync(0xffffffff, l0, 2);
    l1 += __shfl_xor_sync(0xffffffff, l1, 1);
    l1 += __shfl_xor_sync(0xffffffff, l1, 2);
    const float inv0 = 1.0f / l0, inv1 = 1.0f / l1;

    const size_t row0 = (size_t)(b * LL + q0 + wid * 16 + (lane >> 2));
    const size_t row1 = row0 + 8;
    const int colbase = h * HD + (lane & 3) * 2;
    #pragma unroll
    for (int j = 0; j < 8; j++) {
        const int col = colbase + j * 8;
        uint32_t hi, lo;
        split_pack(acc_o[j][0] * inv0, acc_o[j][1] * inv0, hi, lo);
        *(uint32_t*)(Oh + row0 * DD + col) = hi;
        *(uint32_t*)(Ol + row0 * DD + col) = lo;
        split_pack(acc_o[j][2] * inv1, acc_o[j][3] * inv1, hi, lo);
        *(uint32_t*)(Oh + row1 * DD + col) = hi;
        *(uint32_t*)(Ol + row1 * DD + col) = lo;
    }
}

// -------------------------------------------------------------------------
extern "C" void kernel_launch(void* const* d_in, const int* in_sizes, int n_in,
                              void* d_out, int out_size)
{
    const float* x        = (const float*)d_in[0];
    const float* rope_cos = (const float*)d_in[1];
    const float* rope_sin = (const float*)d_in[2];
    const float* W_qkv    = (const float*)d_in[3];
    const float* W_out    = (const float*)d_in[4];
    const float* b_out    = (const float*)d_in[5];
    float* out = (float*)d_out;

    float* qkv;
    cudaGetSymbolAddress((void**)&qkv, g_qkv);

    __nv_bfloat16 *xh, *xl, *wqh, *wql, *woh, *wol, *ath, *atl;
    __nv_bfloat16 *Qh, *Ql, *Kh, *Kl, *Vh, *Vl;
    cudaGetSymbolAddress((void**)&xh,  g_xh);
    cudaGetSymbolAddress((void**)&xl,  g_xl);
    cudaGetSymbolAddress((void**)&wqh, g_wqkvT_h);
    cudaGetSymbolAddress((void**)&wql, g_wqkvT_l);
    cudaGetSymbolAddress((void**)&woh, g_woutT_h);
    cudaGetSymbolAddress((void**)&wol, g_woutT_l);
    cudaGetSymbolAddress((void**)&ath, g_atth);
    cudaGetSymbolAddress((void**)&atl, g_attl);
    cudaGetSymbolAddress((void**)&Qh,  g_Qh);
    cudaGetSymbolAddress((void**)&Ql,  g_Ql);
    cudaGetSymbolAddress((void**)&Kh,  g_Kh);
    cudaGetSymbolAddress((void**)&Kl,  g_Kl);
    cudaGetSymbolAddress((void**)&Vh,  g_Vh);
    cudaGetSymbolAddress((void**)&Vl,  g_Vl);

    cudaFuncSetAttribute(flash_attn, cudaFuncAttributeMaxDynamicSharedMemorySize, ATT_SMEM);

    // 0) operand conversion
    conv_split<<<(MROWS * DD / 4 + 255) / 256, 256>>>(x, xh, xl, MROWS * DD / 4);
    conv_splitT<<<dim3(NQKV / 32, DD / 32), dim3(32, 8)>>>(W_qkv, wqh, wql, DD, NQKV);
    conv_splitT<<<dim3(DD / 32, DD / 32),   dim3(32, 8)>>>(W_out, woh, wol, DD, DD);

    // 1) QKV projection on tensor cores (split bf16, 3-term)
    mma_gemm<false><<<dim3(NQKV / GBN, MROWS / GBM), 256>>>(
        xh, xl, wqh, wql, nullptr, qkv, MROWS, NQKV, DD);

    // 2) RoPE + reshape + split to bf16 [B,H,L,HD]
    {
        const int total = BB * LL * HH * 32;
        rope_split<<<total / 256, 256>>>(qkv, rope_cos, rope_sin,
                                         Qh, Ql, Kh, Kl, Vh, Vl);
    }

    // 3) flash attention (tensor cores) -> split bf16 [B*L, 1024]
    flash_attn<<<dim3(LL / 128, BB * HH), 256, ATT_SMEM>>>(
        Qh, Ql, Kh, Kl, Vh, Vl, ath, atl);

    // 4) output projection + bias
    mma_gemm<true><<<dim3(DD / GBN, MROWS / GBM), 256>>>(
        ath, atl, woh, wol, b_out, out, MROWS, DD, DD);
}